// round 4
// baseline (speedup 1.0000x reference)
#include <cuda_runtime.h>

#define NN 20000
#define NE 320000
#define LDIM 128
#define TILE 64
#define NT 256
#define NLAYERS 5

// -------- scratch (static device allocations; no runtime alloc) --------
__device__ float g_h[NN * LDIM];     // node features
__device__ float g_P[NN * LDIM];     // h @ W1a  (dst-side precontraction)
__device__ float g_Q[NN * LDIM];     // h @ W1b  (src-side precontraction)
__device__ float g_agg[NN * LDIM];   // segment sum accumulator
__device__ float g_e[NE * LDIM];     // encoded edge features (constant over layers)

typedef unsigned long long u64t;

// -------- packed fp32x2 primitives --------
__device__ __forceinline__ void ffma2(u64t& d, u64t a, u64t b) {
    asm("fma.rn.f32x2 %0, %1, %2, %0;" : "+l"(d) : "l"(a), "l"(b));
}
__device__ __forceinline__ u64t pack2(float x, float y) {
    u64t v; asm("mov.b64 %0, {%1, %2};" : "=l"(v) : "f"(x), "f"(y)); return v;
}
__device__ __forceinline__ float2 unpack2(u64t v) {
    float2 f; asm("mov.b64 {%0, %1}, %2;" : "=f"(f.x), "=f"(f.y) : "l"(v)); return f;
}

__device__ __forceinline__ float prelu1(float v, float a) { return v > 0.f ? v : a * v; }

__device__ __forceinline__ void red_add_v4(float* addr, float4 v) {
    asm volatile("red.global.add.v4.f32 [%0], {%1,%2,%3,%4};"
                 :: "l"(addr), "f"(v.x), "f"(v.y), "f"(v.z), "f"(v.w)
                 : "memory");
}

// -------- smem fills (all row-major, coalesced, conflict-free) --------
__device__ __forceinline__ void cp_f4(float* dst, const float* __restrict__ src,
                                      int n, int tid) {
    for (int i = tid * 4; i < n; i += NT * 4)
        *(float4*)(dst + i) = *(const float4*)(src + i);
}

// 64x128 row tile from [nrows,128] (clamped rows), row-major stride 128
__device__ __forceinline__ void fill_rows(float* As, const float* __restrict__ src,
                                          int r0, int nrows, int tid) {
    for (int i = tid * 4; i < TILE * LDIM; i += NT * 4) {
        int r = i >> 7;
        int gr = r0 + r; if (gr >= nrows) gr = nrows - 1;
        *(float4*)(As + i) = *(const float4*)(src + (size_t)gr * LDIM + (i & (LDIM - 1)));
    }
}

// -------- core packed GEMM (k-paired accumulators) --------
// acc[r][j] is f32x2 = (sum over even k, sum over odd k) for output (row_base+r, c0+j).
// As row-major stride AS, Ws row-major [K][128]. K multiple of 4.
template<int K, int AS>
__device__ __forceinline__ void gemm_k4(const float* __restrict__ As,
                                        const float* __restrict__ Ws,
                                        int row_base, int c0, u64t acc[8][4]) {
#pragma unroll 2
    for (int k = 0; k < K; k += 4) {
        float4 w0 = *(const float4*)(Ws + (k + 0) * LDIM + c0);
        float4 w1 = *(const float4*)(Ws + (k + 1) * LDIM + c0);
        float4 w2 = *(const float4*)(Ws + (k + 2) * LDIM + c0);
        float4 w3 = *(const float4*)(Ws + (k + 3) * LDIM + c0);
        u64t wa0 = pack2(w0.x, w1.x), wa1 = pack2(w0.y, w1.y);
        u64t wa2 = pack2(w0.z, w1.z), wa3 = pack2(w0.w, w1.w);
        u64t wb0 = pack2(w2.x, w3.x), wb1 = pack2(w2.y, w3.y);
        u64t wb2 = pack2(w2.z, w3.z), wb3 = pack2(w2.w, w3.w);
#pragma unroll
        for (int r = 0; r < 8; ++r) {
            ulonglong2 a = *(const ulonglong2*)(As + (row_base + r) * AS + k);
            ffma2(acc[r][0], a.x, wa0); ffma2(acc[r][1], a.x, wa1);
            ffma2(acc[r][2], a.x, wa2); ffma2(acc[r][3], a.x, wa3);
            ffma2(acc[r][0], a.y, wb0); ffma2(acc[r][1], a.y, wb1);
            ffma2(acc[r][2], a.y, wb2); ffma2(acc[r][3], a.y, wb3);
        }
    }
}

__device__ __forceinline__ void acc_init(u64t acc[8][4], float4 b) {
#pragma unroll
    for (int r = 0; r < 8; ++r) {
        acc[r][0] = pack2(b.x, 0.f); acc[r][1] = pack2(b.y, 0.f);
        acc[r][2] = pack2(b.z, 0.f); acc[r][3] = pack2(b.w, 0.f);
    }
}

// horizontal add (even+odd k partial sums) -> float4 row vector
__device__ __forceinline__ float4 acc_fin(const u64t a[4]) {
    float2 f0 = unpack2(a[0]), f1 = unpack2(a[1]), f2 = unpack2(a[2]), f3 = unpack2(a[3]);
    return make_float4(f0.x + f0.y, f1.x + f1.y, f2.x + f2.y, f3.x + f3.y);
}

// prelu(acc) -> U (row-major [64][128]), conflict-free float4 stores
__device__ __forceinline__ void store_U(float* U, u64t acc[8][4],
                                        int row_base, int c0, float al) {
#pragma unroll
    for (int r = 0; r < 8; ++r) {
        float4 v = acc_fin(acc[r]);
        v.x = prelu1(v.x, al); v.y = prelu1(v.y, al);
        v.z = prelu1(v.z, al); v.w = prelu1(v.w, al);
        *(float4*)(U + (row_base + r) * LDIM + c0) = v;
    }
}

// ============================ encoder (node / edge) ============================
// K1P = padded K (multiple of 4); zero-pads both A and W rows >= K1.
template<int K1, int K1P>
__global__ __launch_bounds__(NT, 2)
void encoder_kernel(const float* __restrict__ in,
                    const float* __restrict__ w1, const float* __restrict__ b1,
                    const float* __restrict__ aslope,
                    const float* __restrict__ w2, const float* __restrict__ b2,
                    float* __restrict__ out, int nrows) {
    extern __shared__ float sm[];
    float* Ws = sm;                      // [128][128] max
    float* As = sm + LDIM * LDIM;        // [64][K1P] then U [64][128]
    int tid = threadIdx.x;
    int wy = tid >> 5, tx = tid & 31;
    int row_base = wy * 8, c0 = tx * 4;
    int r0 = blockIdx.x * TILE;

    // A tile, zero-padded to K1P
    for (int i = tid; i < TILE * K1P; i += NT) {
        int r = i / K1P, k = i - r * K1P;
        int gr = r0 + r; if (gr >= nrows) gr = nrows - 1;
        As[i] = (k < K1) ? in[(size_t)gr * K1 + k] : 0.f;
    }
    // W1, zero-padded rows
    for (int i = tid; i < K1P * LDIM; i += NT)
        Ws[i] = (i < K1 * LDIM) ? w1[i] : 0.f;
    __syncthreads();

    u64t acc[8][4];
    acc_init(acc, *(const float4*)(b1 + c0));
    gemm_k4<K1P, K1P>(As, Ws, row_base, c0, acc);

    float al = *aslope;
    __syncthreads();
    store_U(As, acc, row_base, c0, al);     // U stride 128 (fits: 32KB buffer)
    cp_f4(Ws, w2, LDIM * LDIM, tid);
    __syncthreads();

    acc_init(acc, *(const float4*)(b2 + c0));
    gemm_k4<LDIM, LDIM>(As, Ws, row_base, c0, acc);

#pragma unroll
    for (int r = 0; r < 8; ++r) {
        int gr = r0 + row_base + r;
        if (gr < nrows) *(float4*)(out + (size_t)gr * LDIM + c0) = acc_fin(acc[r]);
    }
}

// ============================ per-layer: P/Q + zero agg ============================
__global__ __launch_bounds__(NT, 2)
void pq_kernel(const float* __restrict__ wl /* le_w1 layer base [384,128] */) {
    extern __shared__ float sm[];
    float* Ws = sm;
    float* As = sm + LDIM * LDIM;
    int tid = threadIdx.x;
    int wy = tid >> 5, tx = tid & 31;
    int row_base = wy * 8, c0 = tx * 4;
    int r0 = blockIdx.x * TILE;

    fill_rows(As, g_h, r0, NN, tid);
    cp_f4(Ws, wl, LDIM * LDIM, tid);                 // W1a (dst side)
    __syncthreads();

    float4 z = make_float4(0.f, 0.f, 0.f, 0.f);
    u64t acc[8][4];
    acc_init(acc, z);
    gemm_k4<LDIM, LDIM>(As, Ws, row_base, c0, acc);
#pragma unroll
    for (int r = 0; r < 8; ++r) {
        int gr = r0 + row_base + r;
        if (gr < NN) {
            *(float4*)(g_P + (size_t)gr * LDIM + c0) = acc_fin(acc[r]);
            *(float4*)(g_agg + (size_t)gr * LDIM + c0) = z;
        }
    }
    __syncthreads();
    cp_f4(Ws, wl + LDIM * LDIM, LDIM * LDIM, tid);   // W1b (src side)
    __syncthreads();
    acc_init(acc, z);
    gemm_k4<LDIM, LDIM>(As, Ws, row_base, c0, acc);
#pragma unroll
    for (int r = 0; r < 8; ++r) {
        int gr = r0 + row_base + r;
        if (gr < NN) *(float4*)(g_Q + (size_t)gr * LDIM + c0) = acc_fin(acc[r]);
    }
}

// ============================ per-layer: edge messages + scatter ============================
__global__ __launch_bounds__(NT, 2)
void edge_kernel(const int* __restrict__ eidx,
                 const float* __restrict__ wl,    // le_w1 layer base [384,128]
                 const float* __restrict__ b1, const float* __restrict__ aslope,
                 const float* __restrict__ w2, const float* __restrict__ b2) {
    extern __shared__ float sm[];
    float* Ws = sm;
    float* As = sm + LDIM * LDIM;
    int* sdst = (int*)(As + TILE * LDIM);
    int* ssrc = sdst + TILE;
    int tid = threadIdx.x;
    int wy = tid >> 5, tx = tid & 31;
    int row_base = wy * 8, c0 = tx * 4;
    size_t e0 = (size_t)blockIdx.x * TILE;

    cp_f4(As, g_e + e0 * LDIM, TILE * LDIM, tid);    // e tile (contiguous rows)
    cp_f4(Ws, wl + 256 * LDIM, LDIM * LDIM, tid);    // W1c (e side)
    if (tid < TILE) {
        ssrc[tid] = eidx[e0 + tid];        // edge_index[0] = src (x_j)
        sdst[tid] = eidx[NE + e0 + tid];   // edge_index[1] = dst (x_i / agg idx)
    }
    __syncthreads();

    float4 b1v = *(const float4*)(b1 + c0);
    u64t acc[8][4];
#pragma unroll
    for (int r = 0; r < 8; ++r) {
        int d = sdst[row_base + r];
        int s = ssrc[row_base + r];
        float4 P = *(const float4*)(g_P + (size_t)d * LDIM + c0);
        float4 Q = *(const float4*)(g_Q + (size_t)s * LDIM + c0);
        acc[r][0] = pack2(b1v.x + P.x + Q.x, 0.f);
        acc[r][1] = pack2(b1v.y + P.y + Q.y, 0.f);
        acc[r][2] = pack2(b1v.z + P.z + Q.z, 0.f);
        acc[r][3] = pack2(b1v.w + P.w + Q.w, 0.f);
    }
    gemm_k4<LDIM, LDIM>(As, Ws, row_base, c0, acc);

    float al = *aslope;
    __syncthreads();
    store_U(As, acc, row_base, c0, al);
    cp_f4(Ws, w2, LDIM * LDIM, tid);
    __syncthreads();

    acc_init(acc, *(const float4*)(b2 + c0));
    gemm_k4<LDIM, LDIM>(As, Ws, row_base, c0, acc);

    // scatter-add m into agg[dst] (m never materialized)
#pragma unroll
    for (int r = 0; r < 8; ++r)
        red_add_v4(g_agg + (size_t)sdst[row_base + r] * LDIM + c0, acc_fin(acc[r]));
}

// ============================ per-layer: node update ============================
__global__ __launch_bounds__(NT, 2)
void node_kernel(const float* __restrict__ wn1,  // ln_w1 layer base [256,128]
                 const float* __restrict__ b1, const float* __restrict__ aslope,
                 const float* __restrict__ w2, const float* __restrict__ b2) {
    extern __shared__ float sm[];
    float* Ws = sm;
    float* As = sm + LDIM * LDIM;
    int tid = threadIdx.x;
    int wy = tid >> 5, tx = tid & 31;
    int row_base = wy * 8, c0 = tx * 4;
    int r0 = blockIdx.x * TILE;

    fill_rows(As, g_h, r0, NN, tid);
    cp_f4(Ws, wn1, LDIM * LDIM, tid);          // rows 0..127 (h side)
    __syncthreads();

    u64t acc[8][4];
    acc_init(acc, *(const float4*)(b1 + c0));
    gemm_k4<LDIM, LDIM>(As, Ws, row_base, c0, acc);

    __syncthreads();
    fill_rows(As, g_agg, r0, NN, tid);
    cp_f4(Ws, wn1 + LDIM * LDIM, LDIM * LDIM, tid);   // rows 128..255 (agg side)
    __syncthreads();
    gemm_k4<LDIM, LDIM>(As, Ws, row_base, c0, acc);    // accumulate

    float al = *aslope;
    __syncthreads();
    store_U(As, acc, row_base, c0, al);
    cp_f4(Ws, w2, LDIM * LDIM, tid);
    __syncthreads();

    acc_init(acc, *(const float4*)(b2 + c0));
    gemm_k4<LDIM, LDIM>(As, Ws, row_base, c0, acc);

#pragma unroll
    for (int r = 0; r < 8; ++r) {
        int gr = r0 + row_base + r;
        if (gr < NN) {
            float4 hv = *(const float4*)(g_h + (size_t)gr * LDIM + c0);
            float4 u = acc_fin(acc[r]);
            hv.x += u.x; hv.y += u.y; hv.z += u.z; hv.w += u.w;
            *(float4*)(g_h + (size_t)gr * LDIM + c0) = hv;      // h = h + upd
        }
    }
}

// ============================ decoder ============================
__global__ __launch_bounds__(NT, 2)
void dec_kernel(const float* __restrict__ w1, const float* __restrict__ b1,
                const float* __restrict__ aslope,
                const float* __restrict__ w2, const float* __restrict__ b2,
                float* __restrict__ out) {
    extern __shared__ float sm[];
    float* Ws = sm;
    float* As = sm + LDIM * LDIM;
    int tid = threadIdx.x;
    int wy = tid >> 5, tx = tid & 31;
    int row_base = wy * 8, c0 = tx * 4;
    int r0 = blockIdx.x * TILE;

    fill_rows(As, g_h, r0, NN, tid);
    cp_f4(Ws, w1, LDIM * LDIM, tid);
    __syncthreads();

    u64t acc[8][4];
    acc_init(acc, *(const float4*)(b1 + c0));
    gemm_k4<LDIM, LDIM>(As, Ws, row_base, c0, acc);

    float al = *aslope;
    __syncthreads();
    store_U(As, acc, row_base, c0, al);
    __syncthreads();

    for (int idx = tid; idx < TILE * 3; idx += NT) {
        int r = idx / 3, c = idx - r * 3;
        int gr = r0 + r;
        if (gr < NN) {
            float s = b2[c];
#pragma unroll 8
            for (int k = 0; k < LDIM; ++k)
                s = fmaf(As[r * LDIM + k], w2[k * 3 + c], s);
            out[(size_t)gr * 3 + c] = s;
        }
    }
}

// ============================ host ============================
extern "C" void kernel_launch(void* const* d_in, const int* in_sizes, int n_in,
                              void* d_out, int out_size) {
    const float* x          = (const float*)d_in[0];
    const float* edge_attr  = (const float*)d_in[1];
    const int*   edge_index = (const int*)  d_in[2];
    const float* ne_w1 = (const float*)d_in[3];
    const float* ne_b1 = (const float*)d_in[4];
    const float* ne_a  = (const float*)d_in[5];
    const float* ne_w2 = (const float*)d_in[6];
    const float* ne_b2 = (const float*)d_in[7];
    const float* ee_w1 = (const float*)d_in[8];
    const float* ee_b1 = (const float*)d_in[9];
    const float* ee_a  = (const float*)d_in[10];
    const float* ee_w2 = (const float*)d_in[11];
    const float* ee_b2 = (const float*)d_in[12];
    const float* le_w1 = (const float*)d_in[13];
    const float* le_b1 = (const float*)d_in[14];
    const float* le_a  = (const float*)d_in[15];
    const float* le_w2 = (const float*)d_in[16];
    const float* le_b2 = (const float*)d_in[17];
    const float* ln_w1 = (const float*)d_in[18];
    const float* ln_b1 = (const float*)d_in[19];
    const float* ln_a  = (const float*)d_in[20];
    const float* ln_w2 = (const float*)d_in[21];
    const float* ln_b2 = (const float*)d_in[22];
    const float* de_w1 = (const float*)d_in[23];
    const float* de_b1 = (const float*)d_in[24];
    const float* de_a  = (const float*)d_in[25];
    const float* de_w2 = (const float*)d_in[26];
    const float* de_b2 = (const float*)d_in[27];
    float* out = (float*)d_out;

    float *p_h = nullptr, *p_e = nullptr;
    cudaGetSymbolAddress((void**)&p_h, g_h);
    cudaGetSymbolAddress((void**)&p_e, g_e);

    const int SMEM_MAIN = (LDIM * LDIM + TILE * LDIM) * 4;   // 96 KB
    const int SMEM_EDGE = SMEM_MAIN + 2 * TILE * 4;          // + index staging

    cudaFuncSetAttribute((const void*)encoder_kernel<30,32>, cudaFuncAttributeMaxDynamicSharedMemorySize, SMEM_MAIN);
    cudaFuncSetAttribute((const void*)encoder_kernel<4,4>,   cudaFuncAttributeMaxDynamicSharedMemorySize, SMEM_MAIN);
    cudaFuncSetAttribute((const void*)pq_kernel,   cudaFuncAttributeMaxDynamicSharedMemorySize, SMEM_MAIN);
    cudaFuncSetAttribute((const void*)edge_kernel, cudaFuncAttributeMaxDynamicSharedMemorySize, SMEM_EDGE);
    cudaFuncSetAttribute((const void*)node_kernel, cudaFuncAttributeMaxDynamicSharedMemorySize, SMEM_MAIN);
    cudaFuncSetAttribute((const void*)dec_kernel,  cudaFuncAttributeMaxDynamicSharedMemorySize, SMEM_MAIN);

    const int nb_n = (NN + TILE - 1) / TILE;   // 313
    const int nb_e = NE / TILE;                // 5000

    encoder_kernel<30,32><<<nb_n, NT, SMEM_MAIN>>>(x, ne_w1, ne_b1, ne_a, ne_w2, ne_b2, p_h, NN);
    encoder_kernel<4,4>  <<<nb_e, NT, SMEM_MAIN>>>(edge_attr, ee_w1, ee_b1, ee_a, ee_w2, ee_b2, p_e, NE);

    for (int l = 0; l < NLAYERS; ++l) {
        const float* wl = le_w1 + (size_t)l * 384 * LDIM;
        pq_kernel<<<nb_n, NT, SMEM_MAIN>>>(wl);
        edge_kernel<<<nb_e, NT, SMEM_EDGE>>>(edge_index, wl,
                                             le_b1 + l * LDIM, le_a + l,
                                             le_w2 + (size_t)l * LDIM * LDIM,
                                             le_b2 + l * LDIM);
        node_kernel<<<nb_n, NT, SMEM_MAIN>>>(ln_w1 + (size_t)l * 256 * LDIM,
                                             ln_b1 + l * LDIM, ln_a + l,
                                             ln_w2 + (size_t)l * LDIM * LDIM,
                                             ln_b2 + l * LDIM);
    }
    dec_kernel<<<nb_n, NT, SMEM_MAIN>>>(de_w1, de_b1, de_a, de_w2, de_b2, out);
}

// round 5
// speedup vs baseline: 1.3653x; 1.3653x over previous
#include <cuda_runtime.h>

#define NN 20000
#define NE 320000
#define LDIM 128
#define TILE 64
#define NT 256
#define NLAYERS 5

// -------- scratch (static device allocations; no runtime alloc) --------
__device__ float g_h[NN * LDIM];     // node features
__device__ float g_P[NN * LDIM];     // h @ W1a  (dst-side precontraction)
__device__ float g_Q[NN * LDIM];     // h @ W1b  (src-side precontraction)
__device__ float g_agg[NN * LDIM];   // segment sum accumulator
__device__ float g_e[NE * LDIM];     // encoded edge features (constant over layers)

typedef unsigned long long u64t;

// -------- packed fp32x2 primitives --------
__device__ __forceinline__ void ffma2(u64t& d, u64t a, u64t b) {
    asm("fma.rn.f32x2 %0, %1, %2, %0;" : "+l"(d) : "l"(a), "l"(b));
}
__device__ __forceinline__ u64t pack2(float x, float y) {
    u64t v; asm("mov.b64 %0, {%1, %2};" : "=l"(v) : "f"(x), "f"(y)); return v;
}
__device__ __forceinline__ float2 unpack2(u64t v) {
    float2 f; asm("mov.b64 {%0, %1}, %2;" : "=f"(f.x), "=f"(f.y) : "l"(v)); return f;
}

__device__ __forceinline__ float prelu1(float v, float a) { return v > 0.f ? v : a * v; }

__device__ __forceinline__ void red_add_v4(float* addr, float4 v) {
    asm volatile("red.global.add.v4.f32 [%0], {%1,%2,%3,%4};"
                 :: "l"(addr), "f"(v.x), "f"(v.y), "f"(v.z), "f"(v.w)
                 : "memory");
}

// -------- smem fills --------
__device__ __forceinline__ void cp_f4(float* dst, const float* __restrict__ src,
                                      int n, int tid) {
    for (int i = tid * 4; i < n; i += NT * 4)
        *(float4*)(dst + i) = *(const float4*)(src + i);
}

// 64x128 row tile from [nrows,128] (clamped rows), row-major stride 128
__device__ __forceinline__ void fill_rows(float* As, const float* __restrict__ src,
                                          int r0, int nrows, int tid) {
    for (int i = tid * 4; i < TILE * LDIM; i += NT * 4) {
        int r = i >> 7;
        int gr = r0 + r; if (gr >= nrows) gr = nrows - 1;
        *(float4*)(As + i) = *(const float4*)(src + (size_t)gr * LDIM + (i & (LDIM - 1)));
    }
}

// pre-paired W fill: Wp[kp][c] (u64) = (W[2kp][c], W[2kp+1][c]).
// Wp occupies KP*128 u64 = KP*256 floats. Rows k>=K1 are zero (padding).
template<int K1, int K1P>
__device__ __forceinline__ void cp_pairW(float* Wp, const float* __restrict__ w, int tid) {
    constexpr int KP = K1P / 2;
    const float4 z4 = make_float4(0.f, 0.f, 0.f, 0.f);
    for (int i = tid; i < KP * 32; i += NT) {
        int kp = i >> 5;
        int c = (i & 31) * 4;
        int k0 = 2 * kp, k1 = 2 * kp + 1;
        float4 w0 = (k0 < K1) ? *(const float4*)(w + (size_t)k0 * LDIM + c) : z4;
        float4 w1 = (k1 < K1) ? *(const float4*)(w + (size_t)k1 * LDIM + c) : z4;
        float* d = Wp + (size_t)kp * 256 + c * 2;
        *(float4*)(d)     = make_float4(w0.x, w1.x, w0.y, w1.y);
        *(float4*)(d + 4) = make_float4(w0.z, w1.z, w0.w, w1.w);
    }
}

// -------- core packed GEMM (k-paired accumulators, pre-paired W) --------
// acc[r][j] f32x2 = (even-k sum, odd-k sum) for output (row_base+r, c0+j).
// As row-major [64][AS] floats; Wp [KP][128] u64 pairs. KP even.
template<int KP, int AS>
__device__ __forceinline__ void gemm_p(const float* __restrict__ As,
                                       const float* __restrict__ WpF,
                                       int row_base, int c0, u64t acc[8][4]) {
    const u64t* Wp = (const u64t*)WpF;
#pragma unroll 2
    for (int kp = 0; kp < KP; kp += 2) {
        const u64t* wpa = Wp + (size_t)kp * 128 + c0;
        const u64t* wpb = wpa + 128;
        u64t wa0 = wpa[0], wa1 = wpa[1], wa2 = wpa[2], wa3 = wpa[3];
        u64t wb0 = wpb[0], wb1 = wpb[1], wb2 = wpb[2], wb3 = wpb[3];
#pragma unroll
        for (int r = 0; r < 8; ++r) {
            ulonglong2 a = *(const ulonglong2*)(As + (row_base + r) * AS + 2 * kp);
            ffma2(acc[r][0], a.x, wa0); ffma2(acc[r][1], a.x, wa1);
            ffma2(acc[r][2], a.x, wa2); ffma2(acc[r][3], a.x, wa3);
            ffma2(acc[r][0], a.y, wb0); ffma2(acc[r][1], a.y, wb1);
            ffma2(acc[r][2], a.y, wb2); ffma2(acc[r][3], a.y, wb3);
        }
    }
}

__device__ __forceinline__ void acc_init(u64t acc[8][4], float4 b) {
#pragma unroll
    for (int r = 0; r < 8; ++r) {
        acc[r][0] = pack2(b.x, 0.f); acc[r][1] = pack2(b.y, 0.f);
        acc[r][2] = pack2(b.z, 0.f); acc[r][3] = pack2(b.w, 0.f);
    }
}

// horizontal add (even+odd k partial sums) -> float4 row vector
__device__ __forceinline__ float4 acc_fin(const u64t a[4]) {
    float2 f0 = unpack2(a[0]), f1 = unpack2(a[1]), f2 = unpack2(a[2]), f3 = unpack2(a[3]);
    return make_float4(f0.x + f0.y, f1.x + f1.y, f2.x + f2.y, f3.x + f3.y);
}

// prelu(acc) -> U (row-major [64][128]), conflict-free float4 stores
__device__ __forceinline__ void store_U(float* U, u64t acc[8][4],
                                        int row_base, int c0, float al) {
#pragma unroll
    for (int r = 0; r < 8; ++r) {
        float4 v = acc_fin(acc[r]);
        v.x = prelu1(v.x, al); v.y = prelu1(v.y, al);
        v.z = prelu1(v.z, al); v.w = prelu1(v.w, al);
        *(float4*)(U + (row_base + r) * LDIM + c0) = v;
    }
}

// ============================ encoder (node / edge) ============================
template<int K1, int K1P>
__global__ __launch_bounds__(NT, 2)
void encoder_kernel(const float* __restrict__ in,
                    const float* __restrict__ w1, const float* __restrict__ b1,
                    const float* __restrict__ aslope,
                    const float* __restrict__ w2, const float* __restrict__ b2,
                    float* __restrict__ out, int nrows) {
    extern __shared__ float sm[];
    float* Wp = sm;                      // paired W, up to 64KB
    float* As = sm + LDIM * LDIM * 2 / 2;// offset 128*128 floats (64KB)
    int tid = threadIdx.x;
    int wy = tid >> 5, tx = tid & 31;
    int row_base = wy * 8, c0 = tx * 4;
    int r0 = blockIdx.x * TILE;

    // A tile, zero-padded to K1P
    for (int i = tid; i < TILE * K1P; i += NT) {
        int r = i / K1P, k = i - r * K1P;
        int gr = r0 + r; if (gr >= nrows) gr = nrows - 1;
        As[i] = (k < K1) ? in[(size_t)gr * K1 + k] : 0.f;
    }
    cp_pairW<K1, K1P>(Wp, w1, tid);
    __syncthreads();

    u64t acc[8][4];
    acc_init(acc, *(const float4*)(b1 + c0));
    gemm_p<K1P / 2, K1P>(As, Wp, row_base, c0, acc);

    float al = *aslope;
    __syncthreads();
    store_U(As, acc, row_base, c0, al);
    cp_pairW<LDIM, LDIM>(Wp, w2, tid);
    __syncthreads();

    acc_init(acc, *(const float4*)(b2 + c0));
    gemm_p<LDIM / 2, LDIM>(As, Wp, row_base, c0, acc);

#pragma unroll
    for (int r = 0; r < 8; ++r) {
        int gr = r0 + row_base + r;
        if (gr < nrows) *(float4*)(out + (size_t)gr * LDIM + c0) = acc_fin(acc[r]);
    }
}

// ============================ per-layer: P/Q + zero agg ============================
__global__ __launch_bounds__(NT, 2)
void pq_kernel(const float* __restrict__ wl /* le_w1 layer base [384,128] */) {
    extern __shared__ float sm[];
    float* Wp = sm;
    float* As = sm + LDIM * LDIM;
    int tid = threadIdx.x;
    int wy = tid >> 5, tx = tid & 31;
    int row_base = wy * 8, c0 = tx * 4;
    int r0 = blockIdx.x * TILE;

    fill_rows(As, g_h, r0, NN, tid);
    cp_pairW<LDIM, LDIM>(Wp, wl, tid);               // W1a (dst side)
    __syncthreads();

    float4 z = make_float4(0.f, 0.f, 0.f, 0.f);
    u64t acc[8][4];
    acc_init(acc, z);
    gemm_p<LDIM / 2, LDIM>(As, Wp, row_base, c0, acc);
#pragma unroll
    for (int r = 0; r < 8; ++r) {
        int gr = r0 + row_base + r;
        if (gr < NN) {
            *(float4*)(g_P + (size_t)gr * LDIM + c0) = acc_fin(acc[r]);
            *(float4*)(g_agg + (size_t)gr * LDIM + c0) = z;
        }
    }
    __syncthreads();
    cp_pairW<LDIM, LDIM>(Wp, wl + LDIM * LDIM, tid); // W1b (src side)
    __syncthreads();
    acc_init(acc, z);
    gemm_p<LDIM / 2, LDIM>(As, Wp, row_base, c0, acc);
#pragma unroll
    for (int r = 0; r < 8; ++r) {
        int gr = r0 + row_base + r;
        if (gr < NN) *(float4*)(g_Q + (size_t)gr * LDIM + c0) = acc_fin(acc[r]);
    }
}

// ============================ per-layer: edge messages + scatter ============================
__global__ __launch_bounds__(NT, 2)
void edge_kernel(const int* __restrict__ eidx,
                 const float* __restrict__ wl,    // le_w1 layer base [384,128]
                 const float* __restrict__ b1, const float* __restrict__ aslope,
                 const float* __restrict__ w2, const float* __restrict__ b2) {
    extern __shared__ float sm[];
    float* Wp = sm;
    float* As = sm + LDIM * LDIM;
    int* sdst = (int*)(As + TILE * LDIM);
    int* ssrc = sdst + TILE;
    int tid = threadIdx.x;
    int wy = tid >> 5, tx = tid & 31;
    int row_base = wy * 8, c0 = tx * 4;
    size_t e0 = (size_t)blockIdx.x * TILE;

    cp_f4(As, g_e + e0 * LDIM, TILE * LDIM, tid);    // e tile (contiguous rows)
    cp_pairW<LDIM, LDIM>(Wp, wl + 256 * LDIM, tid);  // W1c (e side)
    if (tid < TILE) {
        ssrc[tid] = eidx[e0 + tid];        // edge_index[0] = src (x_j)
        sdst[tid] = eidx[NE + e0 + tid];   // edge_index[1] = dst (x_i / agg idx)
    }
    __syncthreads();

    float4 b1v = *(const float4*)(b1 + c0);
    u64t acc[8][4];
#pragma unroll
    for (int r = 0; r < 8; ++r) {
        int d = sdst[row_base + r];
        int s = ssrc[row_base + r];
        float4 P = *(const float4*)(g_P + (size_t)d * LDIM + c0);
        float4 Q = *(const float4*)(g_Q + (size_t)s * LDIM + c0);
        acc[r][0] = pack2(b1v.x + P.x + Q.x, 0.f);
        acc[r][1] = pack2(b1v.y + P.y + Q.y, 0.f);
        acc[r][2] = pack2(b1v.z + P.z + Q.z, 0.f);
        acc[r][3] = pack2(b1v.w + P.w + Q.w, 0.f);
    }
    gemm_p<LDIM / 2, LDIM>(As, Wp, row_base, c0, acc);

    float al = *aslope;
    __syncthreads();
    store_U(As, acc, row_base, c0, al);
    cp_pairW<LDIM, LDIM>(Wp, w2, tid);
    __syncthreads();

    acc_init(acc, *(const float4*)(b2 + c0));
    gemm_p<LDIM / 2, LDIM>(As, Wp, row_base, c0, acc);

    // scatter-add m into agg[dst] (m never materialized)
#pragma unroll
    for (int r = 0; r < 8; ++r)
        red_add_v4(g_agg + (size_t)sdst[row_base + r] * LDIM + c0, acc_fin(acc[r]));
}

// ============================ per-layer: node update ============================
__global__ __launch_bounds__(NT, 2)
void node_kernel(const float* __restrict__ wn1,  // ln_w1 layer base [256,128]
                 const float* __restrict__ b1, const float* __restrict__ aslope,
                 const float* __restrict__ w2, const float* __restrict__ b2) {
    extern __shared__ float sm[];
    float* Wp = sm;
    float* As = sm + LDIM * LDIM;
    int tid = threadIdx.x;
    int wy = tid >> 5, tx = tid & 31;
    int row_base = wy * 8, c0 = tx * 4;
    int r0 = blockIdx.x * TILE;

    fill_rows(As, g_h, r0, NN, tid);
    cp_pairW<LDIM, LDIM>(Wp, wn1, tid);          // rows 0..127 (h side)
    __syncthreads();

    u64t acc[8][4];
    acc_init(acc, *(const float4*)(b1 + c0));
    gemm_p<LDIM / 2, LDIM>(As, Wp, row_base, c0, acc);

    __syncthreads();
    fill_rows(As, g_agg, r0, NN, tid);
    cp_pairW<LDIM, LDIM>(Wp, wn1 + LDIM * LDIM, tid);   // rows 128..255 (agg side)
    __syncthreads();
    gemm_p<LDIM / 2, LDIM>(As, Wp, row_base, c0, acc);   // accumulate

    float al = *aslope;
    __syncthreads();
    store_U(As, acc, row_base, c0, al);
    cp_pairW<LDIM, LDIM>(Wp, w2, tid);
    __syncthreads();

    acc_init(acc, *(const float4*)(b2 + c0));
    gemm_p<LDIM / 2, LDIM>(As, Wp, row_base, c0, acc);

#pragma unroll
    for (int r = 0; r < 8; ++r) {
        int gr = r0 + row_base + r;
        if (gr < NN) {
            float4 hv = *(const float4*)(g_h + (size_t)gr * LDIM + c0);
            float4 u = acc_fin(acc[r]);
            hv.x += u.x; hv.y += u.y; hv.z += u.z; hv.w += u.w;
            *(float4*)(g_h + (size_t)gr * LDIM + c0) = hv;      // h = h + upd
        }
    }
}

// ============================ decoder ============================
__global__ __launch_bounds__(NT, 2)
void dec_kernel(const float* __restrict__ w1, const float* __restrict__ b1,
                const float* __restrict__ aslope,
                const float* __restrict__ w2, const float* __restrict__ b2,
                float* __restrict__ out) {
    extern __shared__ float sm[];
    float* Wp = sm;
    float* As = sm + LDIM * LDIM;
    int tid = threadIdx.x;
    int wy = tid >> 5, tx = tid & 31;
    int row_base = wy * 8, c0 = tx * 4;
    int r0 = blockIdx.x * TILE;

    fill_rows(As, g_h, r0, NN, tid);
    cp_pairW<LDIM, LDIM>(Wp, w1, tid);
    __syncthreads();

    u64t acc[8][4];
    acc_init(acc, *(const float4*)(b1 + c0));
    gemm_p<LDIM / 2, LDIM>(As, Wp, row_base, c0, acc);

    float al = *aslope;
    __syncthreads();
    store_U(As, acc, row_base, c0, al);
    __syncthreads();

    for (int idx = tid; idx < TILE * 3; idx += NT) {
        int r = idx / 3, c = idx - r * 3;
        int gr = r0 + r;
        if (gr < NN) {
            float s = b2[c];
#pragma unroll 8
            for (int k = 0; k < LDIM; ++k)
                s = fmaf(As[r * LDIM + k], w2[k * 3 + c], s);
            out[(size_t)gr * 3 + c] = s;
        }
    }
}

// ============================ host ============================
extern "C" void kernel_launch(void* const* d_in, const int* in_sizes, int n_in,
                              void* d_out, int out_size) {
    const float* x          = (const float*)d_in[0];
    const float* edge_attr  = (const float*)d_in[1];
    const int*   edge_index = (const int*)  d_in[2];
    const float* ne_w1 = (const float*)d_in[3];
    const float* ne_b1 = (const float*)d_in[4];
    const float* ne_a  = (const float*)d_in[5];
    const float* ne_w2 = (const float*)d_in[6];
    const float* ne_b2 = (const float*)d_in[7];
    const float* ee_w1 = (const float*)d_in[8];
    const float* ee_b1 = (const float*)d_in[9];
    const float* ee_a  = (const float*)d_in[10];
    const float* ee_w2 = (const float*)d_in[11];
    const float* ee_b2 = (const float*)d_in[12];
    const float* le_w1 = (const float*)d_in[13];
    const float* le_b1 = (const float*)d_in[14];
    const float* le_a  = (const float*)d_in[15];
    const float* le_w2 = (const float*)d_in[16];
    const float* le_b2 = (const float*)d_in[17];
    const float* ln_w1 = (const float*)d_in[18];
    const float* ln_b1 = (const float*)d_in[19];
    const float* ln_a  = (const float*)d_in[20];
    const float* ln_w2 = (const float*)d_in[21];
    const float* ln_b2 = (const float*)d_in[22];
    const float* de_w1 = (const float*)d_in[23];
    const float* de_b1 = (const float*)d_in[24];
    const float* de_a  = (const float*)d_in[25];
    const float* de_w2 = (const float*)d_in[26];
    const float* de_b2 = (const float*)d_in[27];
    float* out = (float*)d_out;

    float *p_h = nullptr, *p_e = nullptr;
    cudaGetSymbolAddress((void**)&p_h, g_h);
    cudaGetSymbolAddress((void**)&p_e, g_e);

    const int SMEM_MAIN = (LDIM * LDIM + TILE * LDIM) * 4;   // 96 KB
    const int SMEM_EDGE = SMEM_MAIN + 2 * TILE * 4;          // + index staging

    cudaFuncSetAttribute((const void*)encoder_kernel<30,32>, cudaFuncAttributeMaxDynamicSharedMemorySize, SMEM_MAIN);
    cudaFuncSetAttribute((const void*)encoder_kernel<4,4>,   cudaFuncAttributeMaxDynamicSharedMemorySize, SMEM_MAIN);
    cudaFuncSetAttribute((const void*)pq_kernel,   cudaFuncAttributeMaxDynamicSharedMemorySize, SMEM_MAIN);
    cudaFuncSetAttribute((const void*)edge_kernel, cudaFuncAttributeMaxDynamicSharedMemorySize, SMEM_EDGE);
    cudaFuncSetAttribute((const void*)node_kernel, cudaFuncAttributeMaxDynamicSharedMemorySize, SMEM_MAIN);
    cudaFuncSetAttribute((const void*)dec_kernel,  cudaFuncAttributeMaxDynamicSharedMemorySize, SMEM_MAIN);

    const int nb_n = (NN + TILE - 1) / TILE;   // 313
    const int nb_e = NE / TILE;                // 5000

    encoder_kernel<30,32><<<nb_n, NT, SMEM_MAIN>>>(x, ne_w1, ne_b1, ne_a, ne_w2, ne_b2, p_h, NN);
    encoder_kernel<4,4>  <<<nb_e, NT, SMEM_MAIN>>>(edge_attr, ee_w1, ee_b1, ee_a, ee_w2, ee_b2, p_e, NE);

    for (int l = 0; l < NLAYERS; ++l) {
        const float* wl = le_w1 + (size_t)l * 384 * LDIM;
        pq_kernel<<<nb_n, NT, SMEM_MAIN>>>(wl);
        edge_kernel<<<nb_e, NT, SMEM_EDGE>>>(edge_index, wl,
                                             le_b1 + l * LDIM, le_a + l,
                                             le_w2 + (size_t)l * LDIM * LDIM,
                                             le_b2 + l * LDIM);
        node_kernel<<<nb_n, NT, SMEM_MAIN>>>(ln_w1 + (size_t)l * 256 * LDIM,
                                             ln_b1 + l * LDIM, ln_a + l,
                                             ln_w2 + (size_t)l * LDIM * LDIM,
                                             ln_b2 + l * LDIM);
    }
    dec_kernel<<<nb_n, NT, SMEM_MAIN>>>(de_w1, de_b1, de_a, de_w2, de_b2, out);
}

// round 6
// speedup vs baseline: 1.3664x; 1.0008x over previous
#include <cuda_runtime.h>

#define NN 20000
#define NE 320000
#define LDIM 128
#define TILE 64
#define NT 128
#define NLAYERS 5

// -------- scratch (static device allocations; no runtime alloc) --------
__device__ float g_h[NN * LDIM];     // node features
__device__ float g_P[NN * LDIM];     // h @ W1a  (dst-side precontraction)
__device__ float g_Q[NN * LDIM];     // h @ W1b  (src-side precontraction)
__device__ float g_agg[NN * LDIM];   // segment sum accumulator
__device__ float g_e[NE * LDIM];     // encoded edge features (constant over layers)

typedef unsigned long long u64t;

// -------- packed fp32x2 primitives --------
__device__ __forceinline__ void ffma2(u64t& d, u64t a, u64t b) {
    asm("fma.rn.f32x2 %0, %1, %2, %0;" : "+l"(d) : "l"(a), "l"(b));
}
__device__ __forceinline__ u64t pack2(float x, float y) {
    u64t v; asm("mov.b64 %0, {%1, %2};" : "=l"(v) : "f"(x), "f"(y)); return v;
}
__device__ __forceinline__ float2 unpack2(u64t v) {
    float2 f; asm("mov.b64 {%0, %1}, %2;" : "=f"(f.x), "=f"(f.y) : "l"(v)); return f;
}

__device__ __forceinline__ float prelu1(float v, float a) { return v > 0.f ? v : a * v; }

__device__ __forceinline__ void red_add_v4(float* addr, float4 v) {
    asm volatile("red.global.add.v4.f32 [%0], {%1,%2,%3,%4};"
                 :: "l"(addr), "f"(v.x), "f"(v.y), "f"(v.z), "f"(v.w)
                 : "memory");
}

// -------- smem fills (row-major, coalesced, conflict-free) --------
__device__ __forceinline__ void cp_f4(float* dst, const float* __restrict__ src,
                                      int n, int tid) {
    for (int i = tid * 4; i < n; i += NT * 4)
        *(float4*)(dst + i) = *(const float4*)(src + i);
}

// 64x128 row tile from [nrows,128] (clamped rows)
__device__ __forceinline__ void fill_rows(float* As, const float* __restrict__ src,
                                          int r0, int nrows, int tid) {
    for (int i = tid * 4; i < TILE * LDIM; i += NT * 4) {
        int r = i >> 7;
        int gr = r0 + r; if (gr >= nrows) gr = nrows - 1;
        *(float4*)(As + i) = *(const float4*)(src + (size_t)gr * LDIM + (i & (LDIM - 1)));
    }
}

// -------- core packed GEMM (column-paired accumulators) --------
// Warp covers 16 rows. Lane: lx = lane&15 -> cols lx*8..+7, ly = lane>>4 -> row half.
// acc[r][j] f32x2 = outputs (row_base+r, c0+2j) and (row_base+r, c0+2j+1).
// As row-major [64][AS], Ws row-major [K][128]. K multiple of 4.
template<int K, int AS>
__device__ __forceinline__ void gemm_cp(const float* __restrict__ As,
                                        const float* __restrict__ Ws,
                                        int row_base, int c0, u64t acc[8][4]) {
#pragma unroll 2
    for (int k = 0; k < K; k += 4) {
        float4 av[8];
#pragma unroll
        for (int r = 0; r < 8; ++r)
            av[r] = *(const float4*)(As + (row_base + r) * AS + k);
#pragma unroll
        for (int kk = 0; kk < 4; ++kk) {
            const float* wr = Ws + (k + kk) * LDIM + c0;
            ulonglong2 w0 = *(const ulonglong2*)(wr);
            ulonglong2 w1 = *(const ulonglong2*)(wr + 4);
#pragma unroll
            for (int r = 0; r < 8; ++r) {
                float a = (kk == 0) ? av[r].x : (kk == 1) ? av[r].y
                        : (kk == 2) ? av[r].z : av[r].w;
                u64t ad = pack2(a, a);
                ffma2(acc[r][0], ad, w0.x);
                ffma2(acc[r][1], ad, w0.y);
                ffma2(acc[r][2], ad, w1.x);
                ffma2(acc[r][3], ad, w1.y);
            }
        }
    }
}

// bias init: acc[r][j] = (b[c0+2j], b[c0+2j+1]) -- direct u64 reinterpret of bias
__device__ __forceinline__ void acc_initb(u64t acc[8][4], const float* __restrict__ b, int c0) {
    ulonglong2 b0 = *(const ulonglong2*)(b + c0);
    ulonglong2 b1 = *(const ulonglong2*)(b + c0 + 4);
#pragma unroll
    for (int r = 0; r < 8; ++r) {
        acc[r][0] = b0.x; acc[r][1] = b0.y; acc[r][2] = b1.x; acc[r][3] = b1.y;
    }
}
__device__ __forceinline__ void acc_init0(u64t acc[8][4]) {
#pragma unroll
    for (int r = 0; r < 8; ++r)
        acc[r][0] = acc[r][1] = acc[r][2] = acc[r][3] = 0ull;
}

// acc row -> two float4 (cols c0..c0+3, c0+4..c0+7)
__device__ __forceinline__ void acc_fin2(const u64t a[4], float4& lo, float4& hi) {
    float2 f0 = unpack2(a[0]), f1 = unpack2(a[1]), f2 = unpack2(a[2]), f3 = unpack2(a[3]);
    lo = make_float4(f0.x, f0.y, f1.x, f1.y);
    hi = make_float4(f2.x, f2.y, f3.x, f3.y);
}

// prelu(acc) -> U (row-major [64][128])
__device__ __forceinline__ void store_U(float* U, u64t acc[8][4],
                                        int row_base, int c0, float al) {
#pragma unroll
    for (int r = 0; r < 8; ++r) {
        float4 lo, hi; acc_fin2(acc[r], lo, hi);
        lo.x = prelu1(lo.x, al); lo.y = prelu1(lo.y, al);
        lo.z = prelu1(lo.z, al); lo.w = prelu1(lo.w, al);
        hi.x = prelu1(hi.x, al); hi.y = prelu1(hi.y, al);
        hi.z = prelu1(hi.z, al); hi.w = prelu1(hi.w, al);
        float* p = U + (row_base + r) * LDIM + c0;
        *(float4*)(p)     = lo;
        *(float4*)(p + 4) = hi;
    }
}

// thread -> (row_base, c0) mapping
__device__ __forceinline__ void tmap(int tid, int& row_base, int& c0) {
    int wy = tid >> 5;
    int lane = tid & 31;
    row_base = wy * 16 + (lane >> 4) * 8;
    c0 = (lane & 15) * 8;
}

// ============================ encoder (node / edge) ============================
template<int K1, int K1P>
__global__ __launch_bounds__(NT, 2)
void encoder_kernel(const float* __restrict__ in,
                    const float* __restrict__ w1, const float* __restrict__ b1,
                    const float* __restrict__ aslope,
                    const float* __restrict__ w2, const float* __restrict__ b2,
                    float* __restrict__ out, int nrows) {
    extern __shared__ float sm[];
    float* Ws = sm;                      // [128][128] max
    float* As = sm + LDIM * LDIM;        // [64][K1P] then U [64][128]
    int tid = threadIdx.x;
    int row_base, c0; tmap(tid, row_base, c0);
    int r0 = blockIdx.x * TILE;

    // A tile, zero-padded to K1P
    for (int i = tid; i < TILE * K1P; i += NT) {
        int r = i / K1P, k = i - r * K1P;
        int gr = r0 + r; if (gr >= nrows) gr = nrows - 1;
        As[i] = (k < K1) ? in[(size_t)gr * K1 + k] : 0.f;
    }
    // W1, zero-padded rows
    for (int i = tid; i < K1P * LDIM; i += NT)
        Ws[i] = (i < K1 * LDIM) ? w1[i] : 0.f;
    __syncthreads();

    u64t acc[8][4];
    acc_initb(acc, b1, c0);
    gemm_cp<K1P, K1P>(As, Ws, row_base, c0, acc);

    float al = *aslope;
    __syncthreads();
    store_U(As, acc, row_base, c0, al);
    cp_f4(Ws, w2, LDIM * LDIM, tid);
    __syncthreads();

    acc_initb(acc, b2, c0);
    gemm_cp<LDIM, LDIM>(As, Ws, row_base, c0, acc);

#pragma unroll
    for (int r = 0; r < 8; ++r) {
        int gr = r0 + row_base + r;
        if (gr < nrows) {
            float4 lo, hi; acc_fin2(acc[r], lo, hi);
            *(float4*)(out + (size_t)gr * LDIM + c0)     = lo;
            *(float4*)(out + (size_t)gr * LDIM + c0 + 4) = hi;
        }
    }
}

// ============================ per-layer: P/Q + zero agg ============================
__global__ __launch_bounds__(NT, 2)
void pq_kernel(const float* __restrict__ wl /* le_w1 layer base [384,128] */) {
    extern __shared__ float sm[];
    float* Ws = sm;
    float* As = sm + LDIM * LDIM;
    int tid = threadIdx.x;
    int row_base, c0; tmap(tid, row_base, c0);
    int r0 = blockIdx.x * TILE;

    fill_rows(As, g_h, r0, NN, tid);
    cp_f4(Ws, wl, LDIM * LDIM, tid);                 // W1a (dst side)
    __syncthreads();

    float4 z = make_float4(0.f, 0.f, 0.f, 0.f);
    u64t acc[8][4];
    acc_init0(acc);
    gemm_cp<LDIM, LDIM>(As, Ws, row_base, c0, acc);
#pragma unroll
    for (int r = 0; r < 8; ++r) {
        int gr = r0 + row_base + r;
        if (gr < NN) {
            float4 lo, hi; acc_fin2(acc[r], lo, hi);
            *(float4*)(g_P + (size_t)gr * LDIM + c0)       = lo;
            *(float4*)(g_P + (size_t)gr * LDIM + c0 + 4)   = hi;
            *(float4*)(g_agg + (size_t)gr * LDIM + c0)     = z;
            *(float4*)(g_agg + (size_t)gr * LDIM + c0 + 4) = z;
        }
    }
    __syncthreads();
    cp_f4(Ws, wl + LDIM * LDIM, LDIM * LDIM, tid);   // W1b (src side)
    __syncthreads();
    acc_init0(acc);
    gemm_cp<LDIM, LDIM>(As, Ws, row_base, c0, acc);
#pragma unroll
    for (int r = 0; r < 8; ++r) {
        int gr = r0 + row_base + r;
        if (gr < NN) {
            float4 lo, hi; acc_fin2(acc[r], lo, hi);
            *(float4*)(g_Q + (size_t)gr * LDIM + c0)     = lo;
            *(float4*)(g_Q + (size_t)gr * LDIM + c0 + 4) = hi;
        }
    }
}

// ============================ per-layer: edge messages + scatter ============================
__global__ __launch_bounds__(NT, 2)
void edge_kernel(const int* __restrict__ eidx,
                 const float* __restrict__ wl,    // le_w1 layer base [384,128]
                 const float* __restrict__ b1, const float* __restrict__ aslope,
                 const float* __restrict__ w2, const float* __restrict__ b2) {
    extern __shared__ float sm[];
    float* Ws = sm;
    float* As = sm + LDIM * LDIM;
    int* sdst = (int*)(As + TILE * LDIM);
    int* ssrc = sdst + TILE;
    int tid = threadIdx.x;
    int row_base, c0; tmap(tid, row_base, c0);
    size_t e0 = (size_t)blockIdx.x * TILE;

    cp_f4(As, g_e + e0 * LDIM, TILE * LDIM, tid);    // e tile (contiguous rows)
    cp_f4(Ws, wl + 256 * LDIM, LDIM * LDIM, tid);    // W1c (e side)
    if (tid < TILE) {
        ssrc[tid] = eidx[e0 + tid];        // edge_index[0] = src (x_j)
        sdst[tid] = eidx[NE + e0 + tid];   // edge_index[1] = dst (x_i / agg idx)
    }
    __syncthreads();

    float4 ba = *(const float4*)(b1 + c0);
    float4 bb = *(const float4*)(b1 + c0 + 4);
    u64t acc[8][4];
#pragma unroll
    for (int r = 0; r < 8; ++r) {
        int d = sdst[row_base + r];
        int s = ssrc[row_base + r];
        float4 Pa = *(const float4*)(g_P + (size_t)d * LDIM + c0);
        float4 Pb = *(const float4*)(g_P + (size_t)d * LDIM + c0 + 4);
        float4 Qa = *(const float4*)(g_Q + (size_t)s * LDIM + c0);
        float4 Qb = *(const float4*)(g_Q + (size_t)s * LDIM + c0 + 4);
        acc[r][0] = pack2(ba.x + Pa.x + Qa.x, ba.y + Pa.y + Qa.y);
        acc[r][1] = pack2(ba.z + Pa.z + Qa.z, ba.w + Pa.w + Qa.w);
        acc[r][2] = pack2(bb.x + Pb.x + Qb.x, bb.y + Pb.y + Qb.y);
        acc[r][3] = pack2(bb.z + Pb.z + Qb.z, bb.w + Pb.w + Qb.w);
    }
    gemm_cp<LDIM, LDIM>(As, Ws, row_base, c0, acc);

    float al = *aslope;
    __syncthreads();
    store_U(As, acc, row_base, c0, al);
    cp_f4(Ws, w2, LDIM * LDIM, tid);
    __syncthreads();

    acc_initb(acc, b2, c0);
    gemm_cp<LDIM, LDIM>(As, Ws, row_base, c0, acc);

    // scatter-add m into agg[dst] (m never materialized)
#pragma unroll
    for (int r = 0; r < 8; ++r) {
        int d = sdst[row_base + r];
        float4 lo, hi; acc_fin2(acc[r], lo, hi);
        red_add_v4(g_agg + (size_t)d * LDIM + c0, lo);
        red_add_v4(g_agg + (size_t)d * LDIM + c0 + 4, hi);
    }
}

// ============================ per-layer: node update ============================
__global__ __launch_bounds__(NT, 2)
void node_kernel(const float* __restrict__ wn1,  // ln_w1 layer base [256,128]
                 const float* __restrict__ b1, const float* __restrict__ aslope,
                 const float* __restrict__ w2, const float* __restrict__ b2) {
    extern __shared__ float sm[];
    float* Ws = sm;
    float* As = sm + LDIM * LDIM;
    int tid = threadIdx.x;
    int row_base, c0; tmap(tid, row_base, c0);
    int r0 = blockIdx.x * TILE;

    fill_rows(As, g_h, r0, NN, tid);
    cp_f4(Ws, wn1, LDIM * LDIM, tid);          // rows 0..127 (h side)
    __syncthreads();

    u64t acc[8][4];
    acc_initb(acc, b1, c0);
    gemm_cp<LDIM, LDIM>(As, Ws, row_base, c0, acc);

    __syncthreads();
    fill_rows(As, g_agg, r0, NN, tid);
    cp_f4(Ws, wn1 + LDIM * LDIM, LDIM * LDIM, tid);   // rows 128..255 (agg side)
    __syncthreads();
    gemm_cp<LDIM, LDIM>(As, Ws, row_base, c0, acc);    // accumulate

    float al = *aslope;
    __syncthreads();
    store_U(As, acc, row_base, c0, al);
    cp_f4(Ws, w2, LDIM * LDIM, tid);
    __syncthreads();

    acc_initb(acc, b2, c0);
    gemm_cp<LDIM, LDIM>(As, Ws, row_base, c0, acc);

#pragma unroll
    for (int r = 0; r < 8; ++r) {
        int gr = r0 + row_base + r;
        if (gr < NN) {
            float4 lo, hi; acc_fin2(acc[r], lo, hi);
            float* hp = g_h + (size_t)gr * LDIM + c0;
            float4 h0 = *(float4*)(hp);
            float4 h1 = *(float4*)(hp + 4);
            h0.x += lo.x; h0.y += lo.y; h0.z += lo.z; h0.w += lo.w;
            h1.x += hi.x; h1.y += hi.y; h1.z += hi.z; h1.w += hi.w;
            *(float4*)(hp)     = h0;                       // h = h + upd
            *(float4*)(hp + 4) = h1;
        }
    }
}

// ============================ decoder ============================
__global__ __launch_bounds__(NT, 2)
void dec_kernel(const float* __restrict__ w1, const float* __restrict__ b1,
                const float* __restrict__ aslope,
                const float* __restrict__ w2, const float* __restrict__ b2,
                float* __restrict__ out) {
    extern __shared__ float sm[];
    float* Ws = sm;
    float* As = sm + LDIM * LDIM;
    int tid = threadIdx.x;
    int row_base, c0; tmap(tid, row_base, c0);
    int r0 = blockIdx.x * TILE;

    fill_rows(As, g_h, r0, NN, tid);
    cp_f4(Ws, w1, LDIM * LDIM, tid);
    __syncthreads();

    u64t acc[8][4];
    acc_initb(acc, b1, c0);
    gemm_cp<LDIM, LDIM>(As, Ws, row_base, c0, acc);

    float al = *aslope;
    __syncthreads();
    store_U(As, acc, row_base, c0, al);
    __syncthreads();

    for (int idx = tid; idx < TILE * 3; idx += NT) {
        int r = idx / 3, c = idx - r * 3;
        int gr = r0 + r;
        if (gr < NN) {
            float s = b2[c];
#pragma unroll 8
            for (int k = 0; k < LDIM; ++k)
                s = fmaf(As[r * LDIM + k], w2[k * 3 + c], s);
            out[(size_t)gr * 3 + c] = s;
        }
    }
}

// ============================ host ============================
extern "C" void kernel_launch(void* const* d_in, const int* in_sizes, int n_in,
                              void* d_out, int out_size) {
    const float* x          = (const float*)d_in[0];
    const float* edge_attr  = (const float*)d_in[1];
    const int*   edge_index = (const int*)  d_in[2];
    const float* ne_w1 = (const float*)d_in[3];
    const float* ne_b1 = (const float*)d_in[4];
    const float* ne_a  = (const float*)d_in[5];
    const float* ne_w2 = (const float*)d_in[6];
    const float* ne_b2 = (const float*)d_in[7];
    const float* ee_w1 = (const float*)d_in[8];
    const float* ee_b1 = (const float*)d_in[9];
    const float* ee_a  = (const float*)d_in[10];
    const float* ee_w2 = (const float*)d_in[11];
    const float* ee_b2 = (const float*)d_in[12];
    const float* le_w1 = (const float*)d_in[13];
    const float* le_b1 = (const float*)d_in[14];
    const float* le_a  = (const float*)d_in[15];
    const float* le_w2 = (const float*)d_in[16];
    const float* le_b2 = (const float*)d_in[17];
    const float* ln_w1 = (const float*)d_in[18];
    const float* ln_b1 = (const float*)d_in[19];
    const float* ln_a  = (const float*)d_in[20];
    const float* ln_w2 = (const float*)d_in[21];
    const float* ln_b2 = (const float*)d_in[22];
    const float* de_w1 = (const float*)d_in[23];
    const float* de_b1 = (const float*)d_in[24];
    const float* de_a  = (const float*)d_in[25];
    const float* de_w2 = (const float*)d_in[26];
    const float* de_b2 = (const float*)d_in[27];
    float* out = (float*)d_out;

    float *p_h = nullptr, *p_e = nullptr;
    cudaGetSymbolAddress((void**)&p_h, g_h);
    cudaGetSymbolAddress((void**)&p_e, g_e);

    const int SMEM_MAIN = (LDIM * LDIM + TILE * LDIM) * 4;   // 96 KB
    const int SMEM_EDGE = SMEM_MAIN + 2 * TILE * 4;          // + index staging

    cudaFuncSetAttribute((const void*)encoder_kernel<30,32>, cudaFuncAttributeMaxDynamicSharedMemorySize, SMEM_MAIN);
    cudaFuncSetAttribute((const void*)encoder_kernel<4,4>,   cudaFuncAttributeMaxDynamicSharedMemorySize, SMEM_MAIN);
    cudaFuncSetAttribute((const void*)pq_kernel,   cudaFuncAttributeMaxDynamicSharedMemorySize, SMEM_MAIN);
    cudaFuncSetAttribute((const void*)edge_kernel, cudaFuncAttributeMaxDynamicSharedMemorySize, SMEM_EDGE);
    cudaFuncSetAttribute((const void*)node_kernel, cudaFuncAttributeMaxDynamicSharedMemorySize, SMEM_MAIN);
    cudaFuncSetAttribute((const void*)dec_kernel,  cudaFuncAttributeMaxDynamicSharedMemorySize, SMEM_MAIN);

    const int nb_n = (NN + TILE - 1) / TILE;   // 313
    const int nb_e = NE / TILE;                // 5000

    encoder_kernel<30,32><<<nb_n, NT, SMEM_MAIN>>>(x, ne_w1, ne_b1, ne_a, ne_w2, ne_b2, p_h, NN);
    encoder_kernel<4,4>  <<<nb_e, NT, SMEM_MAIN>>>(edge_attr, ee_w1, ee_b1, ee_a, ee_w2, ee_b2, p_e, NE);

    for (int l = 0; l < NLAYERS; ++l) {
        const float* wl = le_w1 + (size_t)l * 384 * LDIM;
        pq_kernel<<<nb_n, NT, SMEM_MAIN>>>(wl);
        edge_kernel<<<nb_e, NT, SMEM_EDGE>>>(edge_index, wl,
                                             le_b1 + l * LDIM, le_a + l,
                                             le_w2 + (size_t)l * LDIM * LDIM,
                                             le_b2 + l * LDIM);
        node_kernel<<<nb_n, NT, SMEM_MAIN>>>(ln_w1 + (size_t)l * 256 * LDIM,
                                             ln_b1 + l * LDIM, ln_a + l,
                                             ln_w2 + (size_t)l * LDIM * LDIM,
                                             ln_b2 + l * LDIM);
    }
    dec_kernel<<<nb_n, NT, SMEM_MAIN>>>(de_w1, de_b1, de_a, de_w2, de_b2, out);
}